// round 1
// baseline (speedup 1.0000x reference)
#include <cuda_runtime.h>
#include <cuda_bf16.h>
#include <math.h>

// Problem constants (fixed shapes)
#define BB 32
#define TT 2048
#define FF 512
#define HH 512
#define G4 (4*HH)          // 2048 gate columns
#define NCTA 128           // recurrent grid size (all co-resident, 1 CTA/SM)

// ---------------- scratch (no allocations allowed) ----------------
// Xg[t][b][c] : precomputed x@Wi + bias, [T][B][4H] fp32 = 512 MB
__device__ float g_xg[(size_t)TT * BB * G4];
// h ping buffer [B][H]
__device__ float g_h[BB * HH];
// per-step barrier counters
__device__ int g_bar[TT];

// ---------------- barrier-counter init (replay safety) ----------------
__global__ void zero_bar_kernel() {
    int i = blockIdx.x * blockDim.x + threadIdx.x;
    if (i < TT) g_bar[i] = 0;
}

// ---------------- GEMM A: Xg = x @ Wi + bias ----------------
// x: [B*T, F] row-major (row r = b*T + t), Wi: [F, 4H], out Xg[t][b][c]
__global__ __launch_bounds__(256) void gemm_xwi(
    const float* __restrict__ x, const float* __restrict__ Wi,
    const float* __restrict__ bias)
{
    __shared__ float as[8][132];   // [k][row] transposed, padded
    __shared__ float bs[8][128];   // [k][col]

    const int bx = blockIdx.x;   // N tile (16)
    const int by = blockIdx.y;   // M tile (512)
    const int tid = threadIdx.x;
    const int tx = tid & 15;
    const int ty = tid >> 4;
    const int row0 = by * 128;
    const int col0 = bx * 128;

    // load mapping
    const int ar = tid >> 1, ac = tid & 1;   // A: 128 rows x 8 k, one float4 each
    const int br = tid >> 5, bc = tid & 31;  // B: 8 rows x 128 cols, one float4 each

    float acc[8][8];
#pragma unroll
    for (int i = 0; i < 8; i++)
#pragma unroll
        for (int j = 0; j < 8; j++) acc[i][j] = 0.f;

    for (int k0 = 0; k0 < FF; k0 += 8) {
        float4 av = *(const float4*)(x + (size_t)(row0 + ar) * FF + k0 + ac * 4);
        float4 bv = *(const float4*)(Wi + (size_t)(k0 + br) * G4 + col0 + bc * 4);
        __syncthreads();
        as[ac * 4 + 0][ar] = av.x;
        as[ac * 4 + 1][ar] = av.y;
        as[ac * 4 + 2][ar] = av.z;
        as[ac * 4 + 3][ar] = av.w;
        *(float4*)(&bs[br][bc * 4]) = bv;
        __syncthreads();
#pragma unroll
        for (int kk = 0; kk < 8; kk++) {
            float af[8], bf[8];
#pragma unroll
            for (int i = 0; i < 8; i++) af[i] = as[kk][ty * 8 + i];
#pragma unroll
            for (int j = 0; j < 8; j++) bf[j] = bs[kk][tx * 8 + j];
#pragma unroll
            for (int i = 0; i < 8; i++)
#pragma unroll
                for (int j = 0; j < 8; j++) acc[i][j] = fmaf(af[i], bf[j], acc[i][j]);
        }
    }

    // epilogue: scatter to Xg[t][b][c] (+bias)
    const int cbase = col0 + tx * 8;
    float4 bia0 = *(const float4*)(bias + cbase);
    float4 bia1 = *(const float4*)(bias + cbase + 4);
#pragma unroll
    for (int i = 0; i < 8; i++) {
        int r = row0 + ty * 8 + i;
        int bidx = r >> 11;        // /T
        int t = r & (TT - 1);
        float* dst = g_xg + (size_t)t * (BB * G4) + (size_t)bidx * G4 + cbase;
        float4 v0, v1;
        v0.x = acc[i][0] + bia0.x; v0.y = acc[i][1] + bia0.y;
        v0.z = acc[i][2] + bia0.z; v0.w = acc[i][3] + bia0.w;
        v1.x = acc[i][4] + bia1.x; v1.y = acc[i][5] + bia1.y;
        v1.z = acc[i][6] + bia1.z; v1.w = acc[i][7] + bia1.w;
        *(float4*)(dst) = v0;
        *(float4*)(dst + 4) = v1;
    }
}

// ---------------- persistent recurrent kernel ----------------
// 128 CTAs x 256 threads. CTA owns 4 hidden j's (16 z columns, Wh slice in SMEM).
// Thread pair (half 0/1) splits K=512 into two halves of 256; half0 owns state.
// SMEM: hs4[128][33] float4 (h, padded), whs[16][512] float, zp[128][4] float.
#define HS4_PAD 33
#define SMEM_REC_BYTES ((128 * HS4_PAD) * 16 + 16 * 512 * 4 + 128 * 4 * 4)

__device__ __forceinline__ float sigf(float v) { return 1.f / (1.f + expf(-v)); }

__global__ __launch_bounds__(256, 1) void lstm_rec(
    const float* __restrict__ Wh, const float* __restrict__ bias,
    const float* __restrict__ c0, const float* __restrict__ h0,
    float* __restrict__ out)
{
    extern __shared__ float smem[];
    float4* hs4 = (float4*)smem;                         // 128*33 float4
    float* whs = smem + 128 * HS4_PAD * 4;               // 16*512 floats
    float* zp  = whs + 16 * 512;                         // 128*4 floats

    const int tid = threadIdx.x;
    const int cta = blockIdx.x;
    const int j0 = cta * 4;

    // load Wh slice once: whs[(jj*4+g)*512 + k] = Wh[k][g*512 + j0 + jj]
    for (int idx = tid; idx < 16 * 512; idx += 256) {
        int c16 = idx >> 9;
        int k = idx & 511;
        int jj = c16 >> 2, g = c16 & 3;
        whs[idx] = Wh[(size_t)k * G4 + g * HH + j0 + jj];
    }

    const int pair = tid & 127;
    const int half = tid >> 7;
    const int b  = pair >> 2;     // 0..31
    const int jj = pair & 3;      // 0..3
    const int j  = j0 + jj;
    const int kbase4 = half * 64; // float4 k-offset

    // half0 per-thread state
    float creg = 0.f;
    float bw0 = 0.f, bw1 = 0.f, bw2 = 0.f, bw3 = 0.f;
    if (half == 0) {
        creg = c0[b * HH + j];
        bw0 = bias[0 * HH + j];
        bw1 = bias[1 * HH + j];
        bw2 = bias[2 * HH + j];
        bw3 = bias[3 * HH + j];
    }

    float* outc = out;
    float* outh = out + BB * HH;
    float* ys   = out + 2 * BB * HH;

    const float4* w0 = (const float4*)(whs + (jj * 4 + 0) * 512) + kbase4;
    const float4* w1 = (const float4*)(whs + (jj * 4 + 1) * 512) + kbase4;
    const float4* w2 = (const float4*)(whs + (jj * 4 + 2) * 512) + kbase4;
    const float4* w3 = (const float4*)(whs + (jj * 4 + 3) * 512) + kbase4;

    for (int t = 0; t < TT; t++) {
        // cooperative load of h into SMEM (transposed, padded)
        const float4* hsrc = (const float4*)((t == 0) ? h0 : g_h);
#pragma unroll
        for (int m = 0; m < 16; m++) {
            int f4 = tid + m * 256;        // 0..4095 = b*128 + k4
            int bb = f4 >> 7;
            int k4 = f4 & 127;
            float4 v = __ldcv(hsrc + f4);
            hs4[k4 * HS4_PAD + bb] = v;
        }

        // prefetch input-projection gates for this (b, j)
        float xg0 = 0.f, xg1 = 0.f, xg2 = 0.f, xg3 = 0.f;
        if (half == 0) {
            const float* xr = g_xg + (size_t)t * (BB * G4) + (size_t)b * G4 + j;
            xg0 = __ldg(xr + 0 * HH);
            xg1 = __ldg(xr + 1 * HH);
            xg2 = __ldg(xr + 2 * HH);
            xg3 = __ldg(xr + 3 * HH);
        }
        __syncthreads();

        // 4 partial dots over this half's 256 k values
        float a0 = 0.f, a1 = 0.f, a2 = 0.f, a3 = 0.f;
        const float4* hp = hs4 + kbase4 * HS4_PAD + b;
#pragma unroll 8
        for (int k4 = 0; k4 < 64; k4++) {
            float4 h4 = *hp;
            hp += HS4_PAD;
            float4 wv;
            wv = w0[k4];
            a0 = fmaf(h4.x, wv.x, a0); a0 = fmaf(h4.y, wv.y, a0);
            a0 = fmaf(h4.z, wv.z, a0); a0 = fmaf(h4.w, wv.w, a0);
            wv = w1[k4];
            a1 = fmaf(h4.x, wv.x, a1); a1 = fmaf(h4.y, wv.y, a1);
            a1 = fmaf(h4.z, wv.z, a1); a1 = fmaf(h4.w, wv.w, a1);
            wv = w2[k4];
            a2 = fmaf(h4.x, wv.x, a2); a2 = fmaf(h4.y, wv.y, a2);
            a2 = fmaf(h4.z, wv.z, a2); a2 = fmaf(h4.w, wv.w, a2);
            wv = w3[k4];
            a3 = fmaf(h4.x, wv.x, a3); a3 = fmaf(h4.y, wv.y, a3);
            a3 = fmaf(h4.z, wv.z, a3); a3 = fmaf(h4.w, wv.w, a3);
        }

        if (half == 1) {
            zp[pair * 4 + 0] = a0;
            zp[pair * 4 + 1] = a1;
            zp[pair * 4 + 2] = a2;
            zp[pair * 4 + 3] = a3;
        }
        __syncthreads();

        if (half == 0) {
            float z0 = a0 + zp[pair * 4 + 0] + xg0 + bw0;
            float z1 = a1 + zp[pair * 4 + 1] + xg1 + bw1;
            float z2 = a2 + zp[pair * 4 + 2] + xg2 + bw2;
            float z3 = a3 + zp[pair * 4 + 3] + xg3 + bw3;
            float ig = sigf(z0);
            float fg = sigf(z1);
            float gg = tanhf(z2);
            float og = sigf(z3);
            creg = fg * creg + ig * gg;
            float hnew = og * tanhf(creg);
            g_h[b * HH + j] = hnew;
            ys[(size_t)b * (TT * HH) + (size_t)t * HH + j] = hnew;
            if (t == TT - 1) {
                outc[b * HH + j] = creg;
                outh[b * HH + j] = hnew;
            }
        }

        // grid barrier for step t
        __threadfence();
        __syncthreads();
        if (tid == 0) {
            atomicAdd(&g_bar[t], 1);
            volatile int* vb = g_bar;
            while (vb[t] < NCTA) { }
        }
        __syncthreads();
    }
}

// ---------------- launcher ----------------
extern "C" void kernel_launch(void* const* d_in, const int* in_sizes, int n_in,
                              void* d_out, int out_size)
{
    const float* x    = (const float*)d_in[0];
    const float* c0   = (const float*)d_in[1];
    const float* h0   = (const float*)d_in[2];
    const float* Wi   = (const float*)d_in[3];
    const float* Wh   = (const float*)d_in[4];
    const float* bias = (const float*)d_in[5];
    float* out = (float*)d_out;

    cudaFuncSetAttribute(lstm_rec, cudaFuncAttributeMaxDynamicSharedMemorySize,
                         SMEM_REC_BYTES);

    zero_bar_kernel<<<8, 256>>>();
    gemm_xwi<<<dim3(G4 / 128, (BB * TT) / 128), 256>>>(x, Wi, bias);
    lstm_rec<<<NCTA, 256, SMEM_REC_BYTES>>>(Wh, bias, c0, h0, out);
}

// round 3
// speedup vs baseline: 3.5264x; 3.5264x over previous
#include <cuda_runtime.h>
#include <cuda_bf16.h>
#include <math.h>

#define BB 32
#define TT 2048
#define FF 512
#define HH 512
#define G4 (4*HH)
#define NCTA 128

typedef unsigned long long u64;

// ---------------- scratch ----------------
__device__ float g_xg[(size_t)TT * BB * G4];   // [T][B][4H]
__device__ float g_hbuf[2][BB * HH];           // ping-pong h
__device__ int g_bar[TT];

// ---------------- packed f32x2 helpers ----------------
__device__ __forceinline__ u64 f2dup(float v) {
    u64 r; asm("mov.b64 %0, {%1, %1};" : "=l"(r) : "f"(v)); return r;
}
__device__ __forceinline__ u64 fma2(u64 a, u64 b, u64 c) {
    u64 d; asm("fma.rn.f32x2 %0, %1, %2, %3;" : "=l"(d) : "l"(a), "l"(b), "l"(c)); return d;
}
__device__ __forceinline__ u64 add2(u64 a, u64 b) {
    u64 d; asm("add.rn.f32x2 %0, %1, %2;" : "=l"(d) : "l"(a), "l"(b)); return d;
}
__device__ __forceinline__ float2 unpack2(u64 v) {
    float2 r; asm("mov.b64 {%0, %1}, %2;" : "=f"(r.x), "=f"(r.y) : "l"(v)); return r;
}
__device__ __forceinline__ float sigf(float v) { return 1.f / (1.f + expf(-v)); }

// ---------------- barrier init (replay safety) ----------------
__global__ void zero_bar_kernel() {
    int i = blockIdx.x * blockDim.x + threadIdx.x;
    if (i < TT) g_bar[i] = 0;
}

// ---------------- GEMM: Xg = x @ Wi + bias (double-buffered, FFMA2) ----------------
__global__ __launch_bounds__(256) void gemm_xwi(
    const float* __restrict__ x, const float* __restrict__ Wi,
    const float* __restrict__ bias)
{
    __shared__ u64   asd[2][8][128];   // A transposed, value duplicated in both lanes
    __shared__ float bsd[2][8][128];

    const int tid = threadIdx.x;
    const int tx = tid & 15;
    const int ty = tid >> 4;
    const int row0 = blockIdx.y * 128;
    const int col0 = blockIdx.x * 128;

    const int ar = tid >> 1, ac = tid & 1;
    const int br = tid >> 5, bc = tid & 31;

    const float* aptr = x + (size_t)(row0 + ar) * FF + ac * 4;
    const float* bptr = Wi + (size_t)br * G4 + col0 + bc * 4;

    float4 av = *(const float4*)aptr;
    float4 bv = *(const float4*)bptr;

    u64 acc[8][4];
#pragma unroll
    for (int i = 0; i < 8; i++)
#pragma unroll
        for (int j = 0; j < 4; j++) acc[i][j] = 0ull;

    int p = 0;
    for (int s = 0; s < 64; s++) {
        asd[p][ac * 4 + 0][ar] = f2dup(av.x);
        asd[p][ac * 4 + 1][ar] = f2dup(av.y);
        asd[p][ac * 4 + 2][ar] = f2dup(av.z);
        asd[p][ac * 4 + 3][ar] = f2dup(av.w);
        *(float4*)&bsd[p][br][bc * 4] = bv;
        __syncthreads();
        if (s < 63) {
            av = *(const float4*)(aptr + (s + 1) * 8);
            bv = *(const float4*)(bptr + (size_t)(s + 1) * 8 * G4);
        }
#pragma unroll
        for (int kk = 0; kk < 8; kk++) {
            const ulonglong2* ap2 = (const ulonglong2*)&asd[p][kk][ty * 8];
            ulonglong2 q0 = ap2[0], q1 = ap2[1], q2 = ap2[2], q3 = ap2[3];
            const ulonglong2* bp2 = (const ulonglong2*)&bsd[p][kk][tx * 8];
            ulonglong2 r0 = bp2[0], r1 = bp2[1];
            u64 aa[8] = {q0.x, q0.y, q1.x, q1.y, q2.x, q2.y, q3.x, q3.y};
            u64 bb2[4] = {r0.x, r0.y, r1.x, r1.y};
#pragma unroll
            for (int i = 0; i < 8; i++)
#pragma unroll
                for (int j = 0; j < 4; j++)
                    acc[i][j] = fma2(aa[i], bb2[j], acc[i][j]);
        }
        __syncthreads();
        p ^= 1;
    }

    // epilogue: unpack, add bias, scatter to Xg[t][b][c]
    const int cbase = col0 + tx * 8;
    float4 bia0 = *(const float4*)(bias + cbase);
    float4 bia1 = *(const float4*)(bias + cbase + 4);
#pragma unroll
    for (int i = 0; i < 8; i++) {
        int r = row0 + ty * 8 + i;
        int bidx = r >> 11;
        int t = r & (TT - 1);
        float* dst = g_xg + (size_t)t * (BB * G4) + (size_t)bidx * G4 + cbase;
        float2 p0 = unpack2(acc[i][0]);
        float2 p1 = unpack2(acc[i][1]);
        float2 p2 = unpack2(acc[i][2]);
        float2 p3 = unpack2(acc[i][3]);
        float4 v0, v1;
        v0.x = p0.x + bia0.x; v0.y = p0.y + bia0.y;
        v0.z = p1.x + bia0.z; v0.w = p1.y + bia0.w;
        v1.x = p2.x + bia1.x; v1.y = p2.y + bia1.y;
        v1.z = p3.x + bia1.z; v1.w = p3.y + bia1.w;
        *(float4*)(dst) = v0;
        *(float4*)(dst + 4) = v1;
    }
}

// ---------------- persistent recurrent kernel ----------------
// SMEM: hs4 [32 b][129 float4] + wsm4 [128 k4][4 g][4 j] float4 + part2 [256][17] u64
#define SMEM_HS_BYTES   (32 * 129 * 16)          // 66048
#define SMEM_W_BYTES    (128 * 16 * 16)          // 32768
#define SMEM_PART_BYTES (256 * 17 * 8)           // 34816
#define SMEM_REC_BYTES  (SMEM_HS_BYTES + SMEM_W_BYTES + SMEM_PART_BYTES)

__global__ __launch_bounds__(256, 1) void lstm_rec(
    const float* __restrict__ Wh,
    const float* __restrict__ c0, const float* __restrict__ h0,
    float* __restrict__ out)
{
    extern __shared__ char smraw[];
    float4* hs4  = (float4*)smraw;                                  // [32*129]
    float4* wsm4 = (float4*)(smraw + SMEM_HS_BYTES);                // [2048]
    u64*    part2 = (u64*)(smraw + SMEM_HS_BYTES + SMEM_W_BYTES);   // [256*17]

    const int tid = threadIdx.x;
    const int cta = blockIdx.x;
    const int j0 = cta * 4;

    // Wh slice -> SMEM: 8192 floats total.
    // dest float index s = (k4*16 + gate*4 + jj)*4 + kk
    float* wsc = (float*)wsm4;
    for (int s = tid; s < 8192; s += 256) {
        int kk = s & 3, jj = (s >> 2) & 3, gate = (s >> 4) & 3, k4v = s >> 6;
        wsc[s] = Wh[(size_t)(k4v * 4 + kk) * G4 + gate * HH + j0 + jj];
    }

    // dot-thread mapping
    const int ks = tid >> 5, lane = tid & 31, bg = lane >> 2, cg = lane & 3;
    // reducer mapping (tid < 128)
    const int bg_r = tid >> 4, cg_r = (tid >> 2) & 3, ib_r = tid & 3;
    const int b_r = ib_r * 8 + bg_r;
    const int j_r = j0 + cg_r;

    float creg = 0.f;
    if (tid < 128) creg = c0[b_r * HH + j_r];

    float* outc = out;
    float* outh = out + BB * HH;
    float* ys   = out + 2 * BB * HH;

    for (int t = 0; t < TT; t++) {
        // cooperative h load: coalesced gmem, conflict-free smem store (row pad 129)
        const float4* hsrc = (t == 0) ? (const float4*)h0 : (const float4*)g_hbuf[t & 1];
#pragma unroll
        for (int m = 0; m < 16; m++) {
            int f4 = tid + m * 256;
            int bb = f4 >> 7;
            int k4 = f4 & 127;
            hs4[bb * 129 + k4] = __ldcv(hsrc + f4);
        }
        // xg for this step (DRAM latency hides under the dot)
        float xq0 = 0.f, xq1 = 0.f, xq2 = 0.f, xq3 = 0.f;
        if (tid < 128) {
            const float* xr = g_xg + (size_t)t * (BB * G4) + (size_t)b_r * G4 + j_r;
            xq0 = __ldg(xr);
            xq1 = __ldg(xr + HH);
            xq2 = __ldg(xr + 2 * HH);
            xq3 = __ldg(xr + 3 * HH);
        }
        __syncthreads();

        // 4b x 4col x (64 k) outer-product dot, packed f32x2 over k pairs
        u64 acc[4][4];
#pragma unroll
        for (int i = 0; i < 4; i++)
#pragma unroll
            for (int j = 0; j < 4; j++) acc[i][j] = 0ull;

        const int kbase = ks * 16;
#pragma unroll 4
        for (int kq = 0; kq < 16; kq++) {
            int k4 = kbase + kq;
            const ulonglong2* wr = (const ulonglong2*)wsm4 + k4 * 16 + cg;
            ulonglong2 wv0 = wr[0];
            ulonglong2 wv1 = wr[4];
            ulonglong2 wv2 = wr[8];
            ulonglong2 wv3 = wr[12];
            const ulonglong2* hr = (const ulonglong2*)hs4 + bg * 129 + k4;
            ulonglong2 hv0 = hr[0];
            ulonglong2 hv1 = hr[8 * 129];
            ulonglong2 hv2 = hr[16 * 129];
            ulonglong2 hv3 = hr[24 * 129];

            acc[0][0] = fma2(hv0.x, wv0.x, acc[0][0]); acc[0][0] = fma2(hv0.y, wv0.y, acc[0][0]);
            acc[0][1] = fma2(hv0.x, wv1.x, acc[0][1]); acc[0][1] = fma2(hv0.y, wv1.y, acc[0][1]);
            acc[0][2] = fma2(hv0.x, wv2.x, acc[0][2]); acc[0][2] = fma2(hv0.y, wv2.y, acc[0][2]);
            acc[0][3] = fma2(hv0.x, wv3.x, acc[0][3]); acc[0][3] = fma2(hv0.y, wv3.y, acc[0][3]);

            acc[1][0] = fma2(hv1.x, wv0.x, acc[1][0]); acc[1][0] = fma2(hv1.y, wv0.y, acc[1][0]);
            acc[1][1] = fma2(hv1.x, wv1.x, acc[1][1]); acc[1][1] = fma2(hv1.y, wv1.y, acc[1][1]);
            acc[1][2] = fma2(hv1.x, wv2.x, acc[1][2]); acc[1][2] = fma2(hv1.y, wv2.y, acc[1][2]);
            acc[1][3] = fma2(hv1.x, wv3.x, acc[1][3]); acc[1][3] = fma2(hv1.y, wv3.y, acc[1][3]);

            acc[2][0] = fma2(hv2.x, wv0.x, acc[2][0]); acc[2][0] = fma2(hv2.y, wv0.y, acc[2][0]);
            acc[2][1] = fma2(hv2.x, wv1.x, acc[2][1]); acc[2][1] = fma2(hv2.y, wv1.y, acc[2][1]);
            acc[2][2] = fma2(hv2.x, wv2.x, acc[2][2]); acc[2][2] = fma2(hv2.y, wv2.y, acc[2][2]);
            acc[2][3] = fma2(hv2.x, wv3.x, acc[2][3]); acc[2][3] = fma2(hv2.y, wv3.y, acc[2][3]);

            acc[3][0] = fma2(hv3.x, wv0.x, acc[3][0]); acc[3][0] = fma2(hv3.y, wv0.y, acc[3][0]);
            acc[3][1] = fma2(hv3.x, wv1.x, acc[3][1]); acc[3][1] = fma2(hv3.y, wv1.y, acc[3][1]);
            acc[3][2] = fma2(hv3.x, wv2.x, acc[3][2]); acc[3][2] = fma2(hv3.y, wv2.y, acc[3][2]);
            acc[3][3] = fma2(hv3.x, wv3.x, acc[3][3]); acc[3][3] = fma2(hv3.y, wv3.y, acc[3][3]);
        }

        // stash packed partials
#pragma unroll
        for (int i = 0; i < 4; i++)
#pragma unroll
            for (int j = 0; j < 4; j++)
                part2[tid * 17 + i * 4 + j] = acc[i][j];
        __syncthreads();

        if (tid < 128) {
            const int pbase = bg_r * 4 + cg_r;
            float z[4];
#pragma unroll
            for (int g = 0; g < 4; g++) {
                u64 s = part2[pbase * 17 + ib_r * 4 + g];
#pragma unroll
                for (int kk2 = 1; kk2 < 8; kk2++)
                    s = add2(s, part2[(kk2 * 32 + pbase) * 17 + ib_r * 4 + g]);
                float2 uv = unpack2(s);
                z[g] = uv.x + uv.y;
            }
            float zi = z[0] + xq0;
            float zf = z[1] + xq1;
            float zg = z[2] + xq2;
            float zo = z[3] + xq3;
            float ig = sigf(zi);
            float fg = sigf(zf);
            float gg = tanhf(zg);
            float og = sigf(zo);
            creg = fg * creg + ig * gg;
            float hnew = og * tanhf(creg);
            g_hbuf[(t + 1) & 1][b_r * HH + j_r] = hnew;
            ys[(size_t)b_r * (TT * HH) + (size_t)t * HH + j_r] = hnew;
            if (t == TT - 1) {
                outc[b_r * HH + j_r] = creg;
                outh[b_r * HH + j_r] = hnew;
            }
            __threadfence();
        }
        __syncthreads();
        if (tid == 0) {
            atomicAdd(&g_bar[t], 1);
            volatile int* vb = g_bar + t;
            while (*vb < NCTA) { }
        }
        __syncthreads();
    }
}

// ---------------- launcher ----------------
extern "C" void kernel_launch(void* const* d_in, const int* in_sizes, int n_in,
                              void* d_out, int out_size)
{
    const float* x    = (const float*)d_in[0];
    const float* c0   = (const float*)d_in[1];
    const float* h0   = (const float*)d_in[2];
    const float* Wi   = (const float*)d_in[3];
    const float* Wh   = (const float*)d_in[4];
    const float* bias = (const float*)d_in[5];
    float* out = (float*)d_out;

    cudaFuncSetAttribute(lstm_rec, cudaFuncAttributeMaxDynamicSharedMemorySize,
                         SMEM_REC_BYTES);

    zero_bar_kernel<<<8, 256>>>();
    gemm_xwi<<<dim3(G4 / 128, (BB * TT) / 128), 256>>>(x, Wi, bias);
    lstm_rec<<<NCTA, 256, SMEM_REC_BYTES>>>(Wh, c0, h0, out);
}